// round 2
// baseline (speedup 1.0000x reference)
#include <cuda_runtime.h>

// ---------------- problem constants ----------------
#define BB   8
#define EE   512
#define LL   8192
#define KS   5
#define LC   (LL - KS + 1)   // 8188
#define NB2  4094            // ceil(LC/2)
#define NB3  2730            // ceil(LC/3)
#define LOUT 4096            // LL / 2

// ---------------- scratch (no allocation allowed) ----------------
__device__ float g_Wt[EE * KS * EE];            // [(c*5+k)][e] , 512 wide
__device__ float g_y[(size_t)BB * EE * LL];     // conv output, zero-padded tail
__device__ float g_s[BB * LL];                  // per-position score
__device__ float g_att[BB * LL * 3];            // softmax weights

// ---------------- kernel 0: transpose W [e][c][k] -> [(c*5+k)][e] ----------------
__global__ void k_transpose(const float* __restrict__ W) {
    int o = blockIdx.x * 256 + threadIdx.x;     // 2560*512 elements
    if (o >= EE * KS * EE) return;
    int e = o & 511;
    int r = o >> 9;                             // c*5+k
    int c = r / 5;
    int k = r - c * 5;
    g_Wt[o] = W[((size_t)e * EE + c) * KS + k];
}

// ---------------- kernel 1: conv (implicit GEMM, fp32 via f32x2 packed FMA) ----------------
#define BM 128
#define BN 128
#define BKC 8
#define XS_STRIDE 136   // 136*4B = 544B, multiple of 16 -> float4-aligned rows

__global__ void __launch_bounds__(256, 2)
k_conv(const float* __restrict__ x, const float* __restrict__ bias) {
    __shared__ __align__(16) float Ws[BKC * KS * BM];   // [c*5+k][128 e]
    __shared__ __align__(16) float Xs[BKC * XS_STRIDE]; // [c][t window]

    const int b  = blockIdx.z;
    const int e0 = blockIdx.y * BM;
    const int t0 = blockIdx.x * BN;
    const int tid = threadIdx.x;
    const int tx = tid & 15;     // t micro-tile: 8 positions
    const int ty = tid >> 4;     // e micro-tile: 8 channels (4 pairs)

    unsigned long long acc[4][8];
    #pragma unroll
    for (int i = 0; i < 4; i++)
        #pragma unroll
        for (int j = 0; j < 8; j++) acc[i][j] = 0ull;   // (0.f,0.f)

    const float* xb = x + (size_t)b * EE * LL;

    for (int c0 = 0; c0 < EE; c0 += BKC) {
        // ---- load W tile: 40 rows x 128 floats = 1280 float4 ----
        {
            const float4* src = (const float4*)g_Wt;
            float4* dst = (float4*)Ws;
            #pragma unroll
            for (int it = 0; it < 5; it++) {
                int idx = tid + it * 256;          // 0..1279
                int row = idx >> 5;                // 0..39
                int col = idx & 31;
                dst[row * 32 + col] = src[(size_t)(c0 * 5 + row) * (EE / 4) + (e0 >> 2) + col];
            }
        }
        // ---- load X tile: 8 rows x 136 floats (guarded) ----
        {
            int row  = tid >> 5;   // 0..7
            int lane = tid & 31;
            #pragma unroll
            for (int m = 0; m < 5; m++) {
                int col = lane + m * 32;
                if (col < XS_STRIDE) {
                    int gt = t0 + col;
                    float v = 0.f;
                    if (gt < LL) v = xb[(size_t)(c0 + row) * LL + gt];
                    Xs[row * XS_STRIDE + col] = v;
                }
            }
        }
        __syncthreads();

        #pragma unroll
        for (int c = 0; c < BKC; c++) {
            // 12-float sliding window of x for this thread's 8 t-positions
            float w[12];
            {
                const float4* xr = (const float4*)(Xs + c * XS_STRIDE);
                float4 x0 = xr[tx * 2];
                float4 x1 = xr[tx * 2 + 1];
                float4 x2 = xr[tx * 2 + 2];
                w[0]=x0.x; w[1]=x0.y; w[2]=x0.z; w[3]=x0.w;
                w[4]=x1.x; w[5]=x1.y; w[6]=x1.z; w[7]=x1.w;
                w[8]=x2.x; w[9]=x2.y; w[10]=x2.z; w[11]=x2.w;
            }
            #pragma unroll
            for (int k = 0; k < KS; k++) {
                const float* arow = Ws + (c * KS + k) * BM + ty * 8;
                ulonglong2 A0 = *(const ulonglong2*)(arow);
                ulonglong2 A1 = *(const ulonglong2*)(arow + 4);
                unsigned long long a2[4];
                a2[0] = A0.x; a2[1] = A0.y; a2[2] = A1.x; a2[3] = A1.y;
                unsigned long long b2[8];
                #pragma unroll
                for (int j = 0; j < 8; j++) {
                    float v = w[k + j];
                    asm("mov.b64 %0, {%1, %1};" : "=l"(b2[j]) : "f"(v));
                }
                #pragma unroll
                for (int i = 0; i < 4; i++)
                    #pragma unroll
                    for (int j = 0; j < 8; j++)
                        asm("fma.rn.f32x2 %0, %1, %2, %0;"
                            : "+l"(acc[i][j]) : "l"(a2[i]), "l"(b2[j]));
            }
        }
        __syncthreads();
    }

    // ---- epilogue: bias + zero tail (t >= LC) + store ----
    const int tbase = t0 + tx * 8;
    #pragma unroll
    for (int i = 0; i < 4; i++) {
        int er0 = e0 + ty * 8 + 2 * i;
        float b0 = bias[er0];
        float b1 = bias[er0 + 1];
        float v0[8], v1[8];
        #pragma unroll
        for (int j = 0; j < 8; j++) {
            float lo, hi;
            asm("mov.b64 {%0, %1}, %2;" : "=f"(lo), "=f"(hi) : "l"(acc[i][j]));
            bool ok = (tbase + j) < LC;
            v0[j] = ok ? (lo + b0) : 0.f;
            v1[j] = ok ? (hi + b1) : 0.f;
        }
        float* p0 = g_y + ((size_t)b * EE + er0) * LL + tbase;
        float* p1 = p0 + LL;
        *(float4*)(p0)     = make_float4(v0[0], v0[1], v0[2], v0[3]);
        *(float4*)(p0 + 4) = make_float4(v0[4], v0[5], v0[6], v0[7]);
        *(float4*)(p1)     = make_float4(v1[0], v1[1], v1[2], v1[3]);
        *(float4*)(p1 + 4) = make_float4(v1[4], v1[5], v1[6], v1[7]);
    }
}

// ---------------- kernel 2: s[b,t] = sum_e y[b,e,t] * score_w[e] ----------------
__global__ void k_score(const float* __restrict__ score_w) {
    __shared__ float sw[EE];
    int tid = threadIdx.x;
    sw[tid] = score_w[tid];
    sw[tid + 256] = score_w[tid + 256];
    __syncthreads();
    int b = blockIdx.y;
    int t = blockIdx.x * 256 + tid;
    const float* yp = g_y + (size_t)b * EE * LL + t;
    float a0 = 0.f, a1 = 0.f, a2 = 0.f, a3 = 0.f;
    #pragma unroll 4
    for (int e = 0; e < EE; e += 4) {
        a0 += yp[(size_t)(e)     * LL] * sw[e];
        a1 += yp[(size_t)(e + 1) * LL] * sw[e + 1];
        a2 += yp[(size_t)(e + 2) * LL] * sw[e + 2];
        a3 += yp[(size_t)(e + 3) * LL] * sw[e + 3];
    }
    g_s[b * LL + t] = (a0 + a1) + (a2 + a3);
}

// ---------------- kernel 3: softmax over 3 widths per (b,t) ----------------
__global__ void k_att() {
    int b = blockIdx.y;
    int t = blockIdx.x * 256 + threadIdx.x;
    const float* s = g_s + b * LL;
    float sc1 = (t < LC) ? s[t] : 0.f;
    int n2 = t >> 1;
    float sc2 = (n2 < NB2) ? 0.5f * (s[2 * n2] + s[2 * n2 + 1]) : 0.f;
    int n3 = t / 3;
    float sc3 = (n3 < NB3) ? (s[3 * n3] + s[3 * n3 + 1] + s[3 * n3 + 2]) * (1.f / 3.f) : 0.f;
    float m  = fmaxf(sc1, fmaxf(sc2, sc3));
    float e1 = expf(sc1 - m);
    float e2 = expf(sc2 - m);
    float e3 = expf(sc3 - m);
    float inv = 1.f / (e1 + e2 + e3);
    float* ap = g_att + ((size_t)b * LL + t) * 3;
    ap[0] = e1 * inv;
    ap[1] = e2 * inv;
    ap[2] = e3 * inv;
}

// ---------------- kernel 4: blend widths + downsample by 2 ----------------
__global__ void k_combine(float* __restrict__ out) {
    int g  = blockIdx.x * 256 + threadIdx.x;      // 8*512*4096 threads
    int td = g & (LOUT - 1);
    int e  = (g >> 12) & (EE - 1);
    int b  = g >> 21;
    const float* yrow = g_y + ((size_t)b * EE + e) * LL;
    int base = td * 2;                            // t0 = base, t1 = base+1
    float w[6];
    #pragma unroll
    for (int d = 0; d < 6; d++) {
        int idx = base + d - 2;
        w[d] = (idx >= 0 && idx < LL) ? yrow[idx] : 0.f;
    }
    const float* ap = g_att + ((size_t)b * LL + base) * 3;
    float a0 = ap[0], a1 = ap[1], a2 = ap[2], a3 = ap[3], a4 = ap[4], a5 = ap[5];

    float v1_0 = w[2];
    float v1_1 = w[3];
    float v2   = (td < NB2) ? 0.5f * (w[2] + w[3]) : 0.f;

    // width-3 candidate: sliding 3-sums, select by base % 3
    float p0 = w[0] + w[1] + w[2];
    float p1 = w[1] + w[2] + w[3];
    float p2 = w[2] + w[3] + w[4];
    float p3 = w[3] + w[4] + w[5];
    int r = base % 3;
    int n3_0 = base / 3;
    int n3_1 = (base + 1) / 3;
    float s0 = (r == 0) ? p2 : ((r == 1) ? p1 : p0);
    float s1 = (r == 0) ? p2 : ((r == 1) ? p1 : p3);
    float v3_0 = (n3_0 < NB3) ? s0 * (1.f / 3.f) : 0.f;
    float v3_1 = (n3_1 < NB3) ? s1 * (1.f / 3.f) : 0.f;

    out[g] = 0.5f * (a0 * v1_0 + a1 * v2 + a2 * v3_0 +
                     a3 * v1_1 + a4 * v2 + a5 * v3_1);
}

// ---------------- launcher ----------------
extern "C" void kernel_launch(void* const* d_in, const int* in_sizes, int n_in,
                              void* d_out, int out_size) {
    const float* x       = (const float*)d_in[0];
    const float* conv_w  = (const float*)d_in[1];
    const float* conv_b  = (const float*)d_in[2];
    const float* score_w = (const float*)d_in[3];
    float* out = (float*)d_out;

    k_transpose<<<(EE * KS * EE + 255) / 256, 256>>>(conv_w);

    dim3 cg(LL / BN, EE / BM, BB);
    k_conv<<<cg, 256>>>(x, conv_b);

    k_score<<<dim3(LL / 256, BB), 256>>>(score_w);
    k_att<<<dim3(LL / 256, BB), 256>>>();
    k_combine<<<(BB * EE * LOUT) / 256, 256>>>(out);
}

// round 4
// speedup vs baseline: 1.9472x; 1.9472x over previous
#include <cuda_runtime.h>
#include <cuda_bf16.h>
#include <cstdint>

// ---------------- problem constants ----------------
#define BB   8
#define EE   512
#define LL   8192
#define KS   5
#define LC   (LL - KS + 1)   // 8188
#define NB2  4094
#define NB3  2730
#define LOUT 4096

// ---------------- scratch ----------------
// prepped weights: [etile(4)][chunk(32)][tap(5)][split(2)] 4KB swizzled images
__device__ __align__(16) char g_W2[4 * 32 * 10 * 4096];
__device__ float g_y[(size_t)BB * EE * LL];
__device__ float g_spart[4 * BB * LL];
__device__ float g_s[BB * LL];
__device__ float g_att[BB * LL * 3];

// ---------------- helpers ----------------
__device__ __forceinline__ uint32_t smem_to_u32(const void* p) {
    uint32_t a;
    asm("{ .reg .u64 t; cvta.to.shared.u64 t, %1; cvt.u32.u64 %0, t; }" : "=r"(a) : "l"(p));
    return a;
}
__device__ __forceinline__ void cp16(uint32_t s, const void* g) {
    asm volatile("cp.async.cg.shared.global [%0], [%1], 16;" :: "r"(s), "l"(g));
}
#define CP_COMMIT() asm volatile("cp.async.commit_group;")
#define CP_WAIT0()  asm volatile("cp.async.wait_group 0;" ::: "memory")

__device__ __forceinline__ void ldsm4(uint32_t* r, uint32_t addr) {
    asm volatile("ldmatrix.sync.aligned.m8n8.x4.shared.b16 {%0,%1,%2,%3}, [%4];"
        : "=r"(r[0]), "=r"(r[1]), "=r"(r[2]), "=r"(r[3]) : "r"(addr));
}
__device__ __forceinline__ void ldsm4t(uint32_t* r, uint32_t addr) {
    asm volatile("ldmatrix.sync.aligned.m8n8.x4.trans.shared.b16 {%0,%1,%2,%3}, [%4];"
        : "=r"(r[0]), "=r"(r[1]), "=r"(r[2]), "=r"(r[3]) : "r"(addr));
}
__device__ __forceinline__ void mma_bf16(float* d, const uint32_t* a, uint32_t b0, uint32_t b1) {
    asm volatile("mma.sync.aligned.m16n8k16.row.col.f32.bf16.bf16.f32 "
        "{%0,%1,%2,%3}, {%4,%5,%6,%7}, {%8,%9}, {%0,%1,%2,%3};"
        : "+f"(d[0]), "+f"(d[1]), "+f"(d[2]), "+f"(d[3])
        : "r"(a[0]), "r"(a[1]), "r"(a[2]), "r"(a[3]), "r"(b0), "r"(b1));
}

// ---------------- SMEM layout ----------------
#define WBUF_SZ 40960                // 10 images x 4KB per chunk
#define XIMG    6528                 // 136 rows x 48B (16 halves + pad)
#define XBUF0   (2 * WBUF_SZ)        // 81920
#define XBUF(buf, split) (XBUF0 + (buf) * (2 * XIMG) + (split) * XIMG)
#define SW_OFF  (XBUF0 + 4 * XIMG)   // 108032
#define SMEM_TOTAL (SW_OFF + 512)    // 108544

// ---------------- kernel: prep W -> swizzled bf16 hi/lo images ----------------
// image layout: byte = c*256 + ((e>>3)^(c&7))*16 + (e&7)*2  (c:0..15, e:0..127)
__global__ void k_prepW(const float* __restrict__ W) {
    int o = blockIdx.x * 256 + threadIdx.x;   // 4*32*5*16*128 = 1310720
    int e = o & 127;
    int c = (o >> 7) & 15;
    int rest = o >> 11;                       // (etile*32+chunk)*5 + tap
    int tap = rest % 5;
    int ec = rest / 5;                        // etile*32 + chunk
    int e_g = (ec >> 5) * 128 + e;
    int c_g = (ec & 31) * 16 + c;
    float w = W[((size_t)e_g * EE + c_g) * KS + tap];
    __nv_bfloat16 h = __float2bfloat16(w);
    __nv_bfloat16 l = __float2bfloat16(w - __bfloat162float(h));
    size_t base = ((size_t)ec * 10 + tap * 2) * 4096;
    uint32_t off = c * 256 + (((e >> 3) ^ (c & 7)) << 4) + (e & 7) * 2;
    *(__nv_bfloat16*)(g_W2 + base + off) = h;
    *(__nv_bfloat16*)(g_W2 + base + 4096 + off) = l;
}

// ---------------- X tile load / convert helpers ----------------
__device__ __forceinline__ void load_x_regs(const float* __restrict__ xb, int s, int t0,
                                            int wid, int lane, float* v0, float* v1) {
    const float* xr0 = xb + (size_t)(s * 16 + wid * 2) * LL;
    const float* xr1 = xr0 + LL;
    #pragma unroll
    for (int it = 0; it < 5; it++) {
        int t = lane + it * 32;
        bool act = (it < 4) || (lane < 8);
        int tg = t0 + t;
        bool inb = act && (tg < LL);
        v0[it] = inb ? __ldg(xr0 + tg) : 0.f;
        v1[it] = inb ? __ldg(xr1 + tg) : 0.f;
    }
}
__device__ __forceinline__ void store_x_smem(char* smem, uint32_t xoff,
                                             int wid, int lane,
                                             const float* v0, const float* v1) {
    #pragma unroll
    for (int it = 0; it < 5; it++) {
        if (it == 4 && lane >= 8) break;
        int t = lane + it * 32;
        float a = v0[it], b = v1[it];
        __nv_bfloat16 ha = __float2bfloat16(a);
        __nv_bfloat16 hb = __float2bfloat16(b);
        __nv_bfloat16 la = __float2bfloat16(a - __bfloat162float(ha));
        __nv_bfloat16 lb = __float2bfloat16(b - __bfloat162float(hb));
        uint32_t hp = (uint32_t)__bfloat16_as_ushort(ha) |
                      ((uint32_t)__bfloat16_as_ushort(hb) << 16);
        uint32_t lp = (uint32_t)__bfloat16_as_ushort(la) |
                      ((uint32_t)__bfloat16_as_ushort(lb) << 16);
        uint32_t byteoff = (uint32_t)t * 48 + (uint32_t)wid * 4;
        *(uint32_t*)(smem + xoff + byteoff) = hp;
        *(uint32_t*)(smem + xoff + XIMG + byteoff) = lp;
    }
}

// ---------------- kernel: conv via mma.sync bf16 split ----------------
// C[t(128) x e(128)] per CTA; warps: wt (t-half of 64) x we (e-quarter of 32)
__global__ void __launch_bounds__(256, 1)
k_conv_mma(const float* __restrict__ x, const float* __restrict__ bias,
           const float* __restrict__ score_w) {
    extern __shared__ __align__(128) char smem[];
    const uint32_t sb = smem_to_u32(smem);
    const int tid = threadIdx.x, wid = tid >> 5, lane = tid & 31;
    const int b = blockIdx.z;
    const int etile = blockIdx.y;
    const int e0g = etile * 128;
    const int t0 = blockIdx.x * 128;
    const int wt = wid >> 2, we = wid & 3;

    if (tid < 128) ((float*)(smem + SW_OFF))[tid] = score_w[e0g + tid];

    const float* xb = x + (size_t)b * EE * LL;
    const char* wsrc_base = g_W2 + (size_t)etile * 32 * 10 * 4096;

    // per-thread ldmatrix address components
    const int g = lane >> 3, i8 = lane & 7;
    const int a_row0 = wt * 64 + (g & 1) * 8 + i8;       // + mf*16 + tap
    const uint32_t a_col = (uint32_t)(g >> 1) * 16;
    const int b_c = (g & 1) * 8 + i8;
    const int b_e0 = we * 32 + (g >> 1) * 8;
    const uint32_t b_off0 = (uint32_t)b_c * 256 + ((((b_e0) >> 3) ^ (b_c & 7)) << 4);
    const uint32_t b_off1 = (uint32_t)b_c * 256 + ((((b_e0 + 16) >> 3) ^ (b_c & 7)) << 4);

    float acc[64];
    #pragma unroll
    for (int k = 0; k < 64; k++) acc[k] = 0.f;

    // ---- prologue: chunk 0 ----
    {
        const char* wsrc = wsrc_base;
        #pragma unroll
        for (int k = 0; k < 10; k++)
            cp16(sb + (uint32_t)(tid + k * 256) * 16, wsrc + (size_t)(tid + k * 256) * 16);
        CP_COMMIT();
        float v0[5], v1[5];
        load_x_regs(xb, 0, t0, wid, lane, v0, v1);
        store_x_smem(smem, XBUF(0, 0), wid, lane, v0, v1);
        CP_WAIT0();
    }
    __syncthreads();

    for (int s = 0; s < 32; s++) {
        const int buf = s & 1;
        float v0[5], v1[5];
        if (s < 31) {
            const char* wsrc = wsrc_base + (size_t)(s + 1) * 10 * 4096;
            uint32_t wdst = sb + (uint32_t)(buf ^ 1) * WBUF_SZ;
            #pragma unroll
            for (int k = 0; k < 10; k++)
                cp16(wdst + (uint32_t)(tid + k * 256) * 16, wsrc + (size_t)(tid + k * 256) * 16);
            CP_COMMIT();
            load_x_regs(xb, s + 1, t0, wid, lane, v0, v1);
        }

        // ---- compute chunk s ----
        const uint32_t xh = sb + XBUF(buf, 0);
        const uint32_t xl = sb + XBUF(buf, 1);
        const uint32_t wb = sb + (uint32_t)buf * WBUF_SZ;
        #pragma unroll
        for (int tap = 0; tap < 5; tap++) {
            uint32_t bh[8], bl[8];
            {
                uint32_t wh = wb + (uint32_t)(tap * 2) * 4096;
                uint32_t wl = wh + 4096;
                ldsm4t(bh,     wh + b_off0);
                ldsm4t(bh + 4, wh + b_off1);
                ldsm4t(bl,     wl + b_off0);
                ldsm4t(bl + 4, wl + b_off1);
            }
            #pragma unroll
            for (int mf = 0; mf < 4; mf++) {
                const uint32_t ar = (uint32_t)(a_row0 + mf * 16 + tap) * 48 + a_col;
                uint32_t ah[4], al[4];
                ldsm4(ah, xh + ar);
                ldsm4(al, xl + ar);
                #pragma unroll
                for (int nf = 0; nf < 4; nf++) {
                    float* D = acc + (mf * 4 + nf) * 4;
                    mma_bf16(D, ah, bh[nf * 2], bh[nf * 2 + 1]);
                    mma_bf16(D, ah, bl[nf * 2], bl[nf * 2 + 1]);
                    mma_bf16(D, al, bh[nf * 2], bh[nf * 2 + 1]);
                }
            }
        }

        if (s < 31) {
            store_x_smem(smem, XBUF(buf ^ 1, 0), wid, lane, v0, v1);
            CP_WAIT0();
        }
        __syncthreads();
    }

    // ---- epilogue: stage Ds[e][132] with bias + tail-zero ----
    float* Ds = (float*)smem;
    {
        const int tq = lane >> 2, eq = (lane & 3) << 1;
        #pragma unroll
        for (int nf = 0; nf < 4; nf++) {
            const int el = we * 32 + nf * 8 + eq;
            const float b0 = __ldg(bias + e0g + el);
            const float b1 = __ldg(bias + e0g + el + 1);
            #pragma unroll
            for (int mf = 0; mf < 4; mf++) {
                const int tl = wt * 64 + mf * 16 + tq;
                const bool ok0 = (t0 + tl) < LC;
                const bool ok1 = (t0 + tl + 8) < LC;
                const float* A = acc + (mf * 4 + nf) * 4;
                Ds[(size_t)el * 132 + tl]           = ok0 ? A[0] + b0 : 0.f;
                Ds[(size_t)(el + 1) * 132 + tl]     = ok0 ? A[1] + b1 : 0.f;
                Ds[(size_t)el * 132 + tl + 8]       = ok1 ? A[2] + b0 : 0.f;
                Ds[(size_t)(el + 1) * 132 + tl + 8] = ok1 ? A[3] + b1 : 0.f;
            }
        }
    }
    __syncthreads();

    // ---- y store (coalesced) + fused score partials ----
    float* yb = g_y + ((size_t)b * EE + e0g) * LL + t0;
    float* sp = g_spart + (size_t)etile * (BB * LL) + (size_t)b * LL + t0;
    const float* swp = (const float*)(smem + SW_OFF);

    #pragma unroll
    for (int rr = 0; rr < 16; rr++) {
        int e = wid * 16 + rr;
        #pragma unroll
        for (int tb = 0; tb < 4; tb++)
            yb[(size_t)e * LL + tb * 32 + lane] = Ds[(size_t)e * 132 + tb * 32 + lane];
    }
    {
        int tl = tid >> 3, er = tid & 7;
        #pragma unroll
        for (int tb = 0; tb < 4; tb++) {
            float a = 0.f;
            #pragma unroll 4
            for (int k = 0; k < 16; k++) {
                int e = er * 16 + k;
                a += Ds[(size_t)e * 132 + tb * 32 + tl] * swp[e];
            }
            a += __shfl_xor_sync(0xffffffff, a, 1);
            a += __shfl_xor_sync(0xffffffff, a, 2);
            a += __shfl_xor_sync(0xffffffff, a, 4);
            if (er == 0) sp[tb * 32 + tl] = a;
        }
    }
}

// ---------------- kernel: deterministic 4-way score reduce ----------------
__global__ void k_sreduce() {
    int i = blockIdx.x * 256 + threadIdx.x;
    g_s[i] = (g_spart[i] + g_spart[BB * LL + i]) +
             (g_spart[2 * BB * LL + i] + g_spart[3 * BB * LL + i]);
}

// ---------------- kernel: softmax over 3 widths ----------------
__global__ void k_att() {
    int b = blockIdx.y;
    int t = blockIdx.x * 256 + threadIdx.x;
    const float* s = g_s + b * LL;
    float sc1 = (t < LC) ? s[t] : 0.f;
    int n2 = t >> 1;
    float sc2 = (n2 < NB2) ? 0.5f * (s[2 * n2] + s[2 * n2 + 1]) : 0.f;
    int n3 = t / 3;
    float sc3 = (n3 < NB3) ? (s[3 * n3] + s[3 * n3 + 1] + s[3 * n3 + 2]) * (1.f / 3.f) : 0.f;
    float m  = fmaxf(sc1, fmaxf(sc2, sc3));
    float e1 = expf(sc1 - m);
    float e2 = expf(sc2 - m);
    float e3 = expf(sc3 - m);
    float inv = 1.f / (e1 + e2 + e3);
    float* ap = g_att + ((size_t)b * LL + t) * 3;
    ap[0] = e1 * inv;
    ap[1] = e2 * inv;
    ap[2] = e3 * inv;
}

// ---------------- kernel: blend widths + downsample by 2 ----------------
__global__ void k_combine(float* __restrict__ out) {
    int g  = blockIdx.x * 256 + threadIdx.x;
    int td = g & (LOUT - 1);
    int e  = (g >> 12) & (EE - 1);
    int b  = g >> 21;
    const float* yrow = g_y + ((size_t)b * EE + e) * LL;
    int base = td * 2;
    float w[6];
    #pragma unroll
    for (int d = 0; d < 6; d++) {
        int idx = base + d - 2;
        w[d] = (idx >= 0 && idx < LL) ? yrow[idx] : 0.f;
    }
    const float* ap = g_att + ((size_t)b * LL + base) * 3;
    float a0 = ap[0], a1 = ap[1], a2 = ap[2], a3 = ap[3], a4 = ap[4], a5 = ap[5];

    float v1_0 = w[2];
    float v1_1 = w[3];
    float v2   = (td < NB2) ? 0.5f * (w[2] + w[3]) : 0.f;

    float p0 = w[0] + w[1] + w[2];
    float p1 = w[1] + w[2] + w[3];
    float p2 = w[2] + w[3] + w[4];
    float p3 = w[3] + w[4] + w[5];
    int r = base % 3;
    int n3_0 = base / 3;
    int n3_1 = (base + 1) / 3;
    float s0 = (r == 0) ? p2 : ((r == 1) ? p1 : p0);
    float s1 = (r == 0) ? p2 : ((r == 1) ? p1 : p3);
    float v3_0 = (n3_0 < NB3) ? s0 * (1.f / 3.f) : 0.f;
    float v3_1 = (n3_1 < NB3) ? s1 * (1.f / 3.f) : 0.f;

    out[g] = 0.5f * (a0 * v1_0 + a1 * v2 + a2 * v3_0 +
                     a3 * v1_1 + a4 * v2 + a5 * v3_1);
}

// ---------------- launcher ----------------
extern "C" void kernel_launch(void* const* d_in, const int* in_sizes, int n_in,
                              void* d_out, int out_size) {
    const float* x       = (const float*)d_in[0];
    const float* conv_w  = (const float*)d_in[1];
    const float* conv_b  = (const float*)d_in[2];
    const float* score_w = (const float*)d_in[3];
    float* out = (float*)d_out;

    cudaFuncSetAttribute(k_conv_mma, cudaFuncAttributeMaxDynamicSharedMemorySize, SMEM_TOTAL);

    k_prepW<<<5120, 256>>>(conv_w);

    dim3 cg(LL / 128, 4, BB);
    k_conv_mma<<<cg, 256, SMEM_TOTAL>>>(x, conv_b, score_w);

    k_sreduce<<<(BB * LL) / 256, 256>>>();
    k_att<<<dim3(LL / 256, BB), 256>>>();
    k_combine<<<(BB * EE * LOUT) / 256, 256>>>(out);
}

// round 5
// speedup vs baseline: 2.1692x; 1.1140x over previous
#include <cuda_runtime.h>
#include <cuda_bf16.h>
#include <cstdint>

// ---------------- problem constants ----------------
#define BB   8
#define EE   512
#define LL   8192
#define KS   5
#define LC   (LL - KS + 1)   // 8188
#define NB2  4094
#define NB3  2730
#define LOUT 4096

// ---------------- scratch ----------------
// prepped weights: [etile(4)][chunk(32)][tap(5)][split(2)] 4KB swizzled images
__device__ __align__(16) char g_W2[4 * 32 * 10 * 4096];
__device__ float g_y[(size_t)BB * EE * LL];
__device__ float g_spart[4 * BB * LL];
__device__ float g_s[BB * LL];
__device__ float g_att[BB * LL * 3];

// ---------------- helpers ----------------
__device__ __forceinline__ uint32_t smem_to_u32(const void* p) {
    uint32_t a;
    asm("{ .reg .u64 t; cvta.to.shared.u64 t, %1; cvt.u32.u64 %0, t; }" : "=r"(a) : "l"(p));
    return a;
}
__device__ __forceinline__ void cp16(uint32_t s, const void* g) {
    asm volatile("cp.async.cg.shared.global [%0], [%1], 16;" :: "r"(s), "l"(g));
}
#define CP_COMMIT() asm volatile("cp.async.commit_group;")
#define CP_WAIT0()  asm volatile("cp.async.wait_group 0;" ::: "memory")

__device__ __forceinline__ void ldsm4(uint32_t* r, uint32_t addr) {
    asm volatile("ldmatrix.sync.aligned.m8n8.x4.shared.b16 {%0,%1,%2,%3}, [%4];"
        : "=r"(r[0]), "=r"(r[1]), "=r"(r[2]), "=r"(r[3]) : "r"(addr));
}
__device__ __forceinline__ void ldsm4t(uint32_t* r, uint32_t addr) {
    asm volatile("ldmatrix.sync.aligned.m8n8.x4.trans.shared.b16 {%0,%1,%2,%3}, [%4];"
        : "=r"(r[0]), "=r"(r[1]), "=r"(r[2]), "=r"(r[3]) : "r"(addr));
}
__device__ __forceinline__ void mma_bf16(float* d, const uint32_t* a, uint32_t b0, uint32_t b1) {
    asm volatile("mma.sync.aligned.m16n8k16.row.col.f32.bf16.bf16.f32 "
        "{%0,%1,%2,%3}, {%4,%5,%6,%7}, {%8,%9}, {%0,%1,%2,%3};"
        : "+f"(d[0]), "+f"(d[1]), "+f"(d[2]), "+f"(d[3])
        : "r"(a[0]), "r"(a[1]), "r"(a[2]), "r"(a[3]), "r"(b0), "r"(b1));
}

// ---------------- SMEM layout ----------------
#define WBUF_SZ 40960                 // 10 images x 4KB per chunk
#define XBUF0   (2 * WBUF_SZ)         // 81920
#define XIMG    12672                 // 264 rows x 48B (16 bf16 + 16B pad)
#define XBUF(buf, split) (XBUF0 + ((buf) * 2 + (split)) * XIMG)
#define SW_OFF  (XBUF0 + 4 * XIMG)    // 132608
#define SMEM_TOTAL (SW_OFF + 512)     // 133120

// ---------------- kernel: prep W -> swizzled bf16 hi/lo images ----------------
// image layout: byte = c*256 + ((e>>3)^(c&7))*16 + (e&7)*2  (c:0..15, e:0..127)
__global__ void k_prepW(const float* __restrict__ W) {
    int o = blockIdx.x * 256 + threadIdx.x;   // 4*32*5*16*128 = 1310720
    int e = o & 127;
    int c = (o >> 7) & 15;
    int rest = o >> 11;
    int tap = rest % 5;
    int ec = rest / 5;                        // etile*32 + chunk
    int e_g = (ec >> 5) * 128 + e;
    int c_g = (ec & 31) * 16 + c;
    float w = W[((size_t)e_g * EE + c_g) * KS + tap];
    __nv_bfloat16 h = __float2bfloat16(w);
    __nv_bfloat16 l = __float2bfloat16(w - __bfloat162float(h));
    size_t base = ((size_t)ec * 10 + tap * 2) * 4096;
    uint32_t off = c * 256 + (((e >> 3) ^ (c & 7)) << 4) + (e & 7) * 2;
    *(__nv_bfloat16*)(g_W2 + base + off) = h;
    *(__nv_bfloat16*)(g_W2 + base + 4096 + off) = l;
}

// ---------------- X tile load / convert helpers (264 rows) ----------------
__device__ __forceinline__ void load_x_regs(const float* __restrict__ xb, int s, int t0,
                                            int wid, int lane, float* v0, float* v1) {
    const float* xr0 = xb + (size_t)(s * 16 + wid * 2) * LL;
    const float* xr1 = xr0 + LL;
    #pragma unroll
    for (int it = 0; it < 9; it++) {
        int t = lane + it * 32;
        bool act = (it < 8) || (lane < 8);
        int tg = t0 + t;
        bool inb = act && (tg < LL);
        v0[it] = inb ? __ldg(xr0 + tg) : 0.f;
        v1[it] = inb ? __ldg(xr1 + tg) : 0.f;
    }
}
__device__ __forceinline__ void store_x_smem(char* smem, uint32_t xoff,
                                             int wid, int lane,
                                             const float* v0, const float* v1) {
    #pragma unroll
    for (int it = 0; it < 9; it++) {
        if (it == 8 && lane >= 8) break;
        int t = lane + it * 32;
        float a = v0[it], b = v1[it];
        __nv_bfloat16 ha = __float2bfloat16(a);
        __nv_bfloat16 hb = __float2bfloat16(b);
        __nv_bfloat16 la = __float2bfloat16(a - __bfloat162float(ha));
        __nv_bfloat16 lb = __float2bfloat16(b - __bfloat162float(hb));
        uint32_t hp = (uint32_t)__bfloat16_as_ushort(ha) |
                      ((uint32_t)__bfloat16_as_ushort(hb) << 16);
        uint32_t lp = (uint32_t)__bfloat16_as_ushort(la) |
                      ((uint32_t)__bfloat16_as_ushort(lb) << 16);
        uint32_t byteoff = (uint32_t)t * 48 + (uint32_t)wid * 4;
        *(uint32_t*)(smem + xoff + byteoff) = hp;
        *(uint32_t*)(smem + xoff + XIMG + byteoff) = lp;
    }
}

// ---------------- kernel: conv via mma.sync, CTA 256t x 128e, warp 64x64 ----------------
__global__ void __launch_bounds__(256, 1)
k_conv_mma(const float* __restrict__ x, const float* __restrict__ bias,
           const float* __restrict__ score_w) {
    extern __shared__ __align__(128) char smem[];
    const uint32_t sb = smem_to_u32(smem);
    const int tid = threadIdx.x, wid = tid >> 5, lane = tid & 31;
    const int b = blockIdx.z;
    const int etile = blockIdx.y;
    const int e0g = etile * 128;
    const int t0 = blockIdx.x * 256;
    const int wt = wid >> 1;         // 0..3 : 64-t slice
    const int we = wid & 1;          // 0..1 : 64-e slice

    if (tid < 128) ((float*)(smem + SW_OFF))[tid] = score_w[e0g + tid];

    const float* xb = x + (size_t)b * EE * LL;
    const char* wsrc_base = g_W2 + (size_t)etile * 32 * 10 * 4096;

    // ldmatrix address components
    const int g = lane >> 3, i8 = lane & 7;
    const int a_row0 = wt * 64 + (g & 1) * 8 + i8;       // + mf*16 + tap
    const uint32_t a_col = (uint32_t)(g >> 1) * 16;
    const int b_c = (g & 1) * 8 + i8;
    const int b_e0 = we * 64 + (g >> 1) * 8;
    uint32_t boff[4];
    #pragma unroll
    for (int eb = 0; eb < 4; eb++) {
        int be = b_e0 + eb * 16;
        boff[eb] = (uint32_t)b_c * 256 + ((((be) >> 3) ^ (b_c & 7)) << 4);
    }

    float acc[128];
    #pragma unroll
    for (int k = 0; k < 128; k++) acc[k] = 0.f;

    // ---- prologue: chunk 0 ----
    {
        #pragma unroll
        for (int k = 0; k < 10; k++)
            cp16(sb + (uint32_t)(tid + k * 256) * 16, wsrc_base + (size_t)(tid + k * 256) * 16);
        CP_COMMIT();
        float v0[9], v1[9];
        load_x_regs(xb, 0, t0, wid, lane, v0, v1);
        store_x_smem(smem, XBUF(0, 0), wid, lane, v0, v1);
        CP_WAIT0();
    }
    __syncthreads();

    for (int s = 0; s < 32; s++) {
        const int buf = s & 1;
        float v0[9], v1[9];
        if (s < 31) {
            const char* wsrc = wsrc_base + (size_t)(s + 1) * 10 * 4096;
            uint32_t wdst = sb + (uint32_t)(buf ^ 1) * WBUF_SZ;
            #pragma unroll
            for (int k = 0; k < 10; k++)
                cp16(wdst + (uint32_t)(tid + k * 256) * 16, wsrc + (size_t)(tid + k * 256) * 16);
            CP_COMMIT();
            load_x_regs(xb, s + 1, t0, wid, lane, v0, v1);
        }

        // ---- compute chunk s ----
        const uint32_t xh = sb + XBUF(buf, 0);
        const uint32_t xl = sb + XBUF(buf, 1);
        const uint32_t wb = sb + (uint32_t)buf * WBUF_SZ;
        #pragma unroll
        for (int tap = 0; tap < 5; tap++) {
            // A fragments for all 4 mf (reused across 8 nf)
            uint32_t ah[4][4], al[4][4];
            #pragma unroll
            for (int mf = 0; mf < 4; mf++) {
                const uint32_t ar = (uint32_t)(a_row0 + mf * 16 + tap) * 48 + a_col;
                ldsm4(ah[mf], xh + ar);
                ldsm4(al[mf], xl + ar);
            }
            const uint32_t wh = wb + (uint32_t)(tap * 2) * 4096;
            const uint32_t wl = wh + 4096;
            #pragma unroll
            for (int eb = 0; eb < 4; eb++) {
                uint32_t bh[4], bl[4];
                ldsm4t(bh, wh + boff[eb]);
                ldsm4t(bl, wl + boff[eb]);
                #pragma unroll
                for (int mf = 0; mf < 4; mf++) {
                    #pragma unroll
                    for (int sub = 0; sub < 2; sub++) {
                        float* D = acc + (mf * 8 + eb * 2 + sub) * 4;
                        mma_bf16(D, ah[mf], bh[sub * 2], bh[sub * 2 + 1]);
                        mma_bf16(D, ah[mf], bl[sub * 2], bl[sub * 2 + 1]);
                        mma_bf16(D, al[mf], bh[sub * 2], bh[sub * 2 + 1]);
                    }
                }
            }
        }

        if (s < 31) {
            store_x_smem(smem, XBUF(buf ^ 1, 0), wid, lane, v0, v1);
            CP_WAIT0();
        }
        __syncthreads();
    }

    // ---- epilogue: two t-halves of 128, staged in Ds[128e][132t] ----
    float* Ds = (float*)smem;
    const float* swp = (const float*)(smem + SW_OFF);
    const int tq = lane >> 2, eq = (lane & 3) << 1;
    float* sp = g_spart + (size_t)etile * (BB * LL) + (size_t)b * LL + t0;

    #pragma unroll
    for (int p = 0; p < 2; p++) {
        __syncthreads();
        if ((wt >> 1) == p) {
            const int wrow = wt & 1;
            #pragma unroll
            for (int nf = 0; nf < 8; nf++) {
                const int el = we * 64 + nf * 8 + eq;
                const float b0 = __ldg(bias + e0g + el);
                const float b1 = __ldg(bias + e0g + el + 1);
                #pragma unroll
                for (int mf = 0; mf < 4; mf++) {
                    const int tl = wrow * 64 + mf * 16 + tq;
                    const int tg = t0 + p * 128 + tl;
                    const bool ok0 = tg < LC;
                    const bool ok1 = (tg + 8) < LC;
                    const float* A = acc + (mf * 8 + nf) * 4;
                    Ds[(size_t)el * 132 + tl]           = ok0 ? A[0] + b0 : 0.f;
                    Ds[(size_t)(el + 1) * 132 + tl]     = ok0 ? A[1] + b1 : 0.f;
                    Ds[(size_t)el * 132 + tl + 8]       = ok1 ? A[2] + b0 : 0.f;
                    Ds[(size_t)(el + 1) * 132 + tl + 8] = ok1 ? A[3] + b1 : 0.f;
                }
            }
        }
        __syncthreads();

        // y store (coalesced)
        float* yb = g_y + ((size_t)b * EE + e0g) * LL + t0 + p * 128;
        #pragma unroll
        for (int rr = 0; rr < 16; rr++) {
            int e = wid * 16 + rr;
            #pragma unroll
            for (int tb = 0; tb < 4; tb++)
                yb[(size_t)e * LL + tb * 32 + lane] = Ds[(size_t)e * 132 + tb * 32 + lane];
        }
        // fused score partials
        {
            int tl = tid >> 3, er = tid & 7;
            #pragma unroll
            for (int tb = 0; tb < 4; tb++) {
                float a = 0.f;
                #pragma unroll 4
                for (int k = 0; k < 16; k++) {
                    int e = er * 16 + k;
                    a += Ds[(size_t)e * 132 + tb * 32 + tl] * swp[e];
                }
                a += __shfl_xor_sync(0xffffffff, a, 1);
                a += __shfl_xor_sync(0xffffffff, a, 2);
                a += __shfl_xor_sync(0xffffffff, a, 4);
                if (er == 0) sp[p * 128 + tb * 32 + tl] = a;
            }
        }
    }
}

// ---------------- kernel: deterministic 4-way score reduce ----------------
__global__ void k_sreduce() {
    int i = blockIdx.x * 256 + threadIdx.x;
    g_s[i] = (g_spart[i] + g_spart[BB * LL + i]) +
             (g_spart[2 * BB * LL + i] + g_spart[3 * BB * LL + i]);
}

// ---------------- kernel: softmax over 3 widths ----------------
__global__ void k_att() {
    int b = blockIdx.y;
    int t = blockIdx.x * 256 + threadIdx.x;
    const float* s = g_s + b * LL;
    float sc1 = (t < LC) ? s[t] : 0.f;
    int n2 = t >> 1;
    float sc2 = (n2 < NB2) ? 0.5f * (s[2 * n2] + s[2 * n2 + 1]) : 0.f;
    int n3 = t / 3;
    float sc3 = (n3 < NB3) ? (s[3 * n3] + s[3 * n3 + 1] + s[3 * n3 + 2]) * (1.f / 3.f) : 0.f;
    float m  = fmaxf(sc1, fmaxf(sc2, sc3));
    float e1 = expf(sc1 - m);
    float e2 = expf(sc2 - m);
    float e3 = expf(sc3 - m);
    float inv = 1.f / (e1 + e2 + e3);
    float* ap = g_att + ((size_t)b * LL + t) * 3;
    ap[0] = e1 * inv;
    ap[1] = e2 * inv;
    ap[2] = e3 * inv;
}

// ---------------- kernel: blend widths + downsample (att cached in smem) ----------------
__global__ void k_combine(float* __restrict__ out) {
    // grid: (LOUT/128, BB), block 256
    __shared__ float satt[768];
    const int tid = threadIdx.x;
    const int b = blockIdx.y;
    const int tdblk = blockIdx.x;
    const int tbase = tdblk * 256;                   // t range covered: [tbase, tbase+256)
    const float* ag = g_att + ((size_t)b * LL + tbase) * 3;
    for (int i = tid; i < 768; i += 256) satt[i] = ag[i];
    __syncthreads();

    const int tdl = tid & 127;
    const int td = tdblk * 128 + tdl;
    const int baseg = td * 2;
    const int basel = tdl * 2;

    const float a0 = satt[basel * 3 + 0], a1 = satt[basel * 3 + 1], a2 = satt[basel * 3 + 2];
    const float a3 = satt[basel * 3 + 3], a4 = satt[basel * 3 + 4], a5 = satt[basel * 3 + 5];

    // width-3 selection precompute (e-independent)
    const int r = baseg % 3;
    const bool ok3_0 = (baseg / 3) < NB3;
    const bool ok3_1 = ((baseg + 1) / 3) < NB3;
    const bool ok2 = td < NB2;

    for (int e = (tid >> 7); e < EE; e += 2) {
        const float* yrow = g_y + ((size_t)b * EE + e) * LL;
        float w[6];
        #pragma unroll
        for (int d = 0; d < 6; d++) {
            int idx = baseg + d - 2;
            w[d] = (idx >= 0 && idx < LL) ? yrow[idx] : 0.f;
        }
        float v1_0 = w[2];
        float v1_1 = w[3];
        float v2   = ok2 ? 0.5f * (w[2] + w[3]) : 0.f;

        float p0 = w[0] + w[1] + w[2];
        float p1 = w[1] + w[2] + w[3];
        float p2 = w[2] + w[3] + w[4];
        float p3 = w[3] + w[4] + w[5];
        float s0 = (r == 0) ? p2 : ((r == 1) ? p1 : p0);
        float s1 = (r == 0) ? p2 : ((r == 1) ? p1 : p3);
        float v3_0 = ok3_0 ? s0 * (1.f / 3.f) : 0.f;
        float v3_1 = ok3_1 ? s1 * (1.f / 3.f) : 0.f;

        out[((size_t)b * EE + e) * LOUT + td] =
            0.5f * (a0 * v1_0 + a1 * v2 + a2 * v3_0 +
                    a3 * v1_1 + a4 * v2 + a5 * v3_1);
    }
}

// ---------------- launcher ----------------
extern "C" void kernel_launch(void* const* d_in, const int* in_sizes, int n_in,
                              void* d_out, int out_size) {
    const float* x       = (const float*)d_in[0];
    const float* conv_w  = (const float*)d_in[1];
    const float* conv_b  = (const float*)d_in[2];
    const float* score_w = (const float*)d_in[3];
    float* out = (float*)d_out;

    cudaFuncSetAttribute(k_conv_mma, cudaFuncAttributeMaxDynamicSharedMemorySize, SMEM_TOTAL);

    k_prepW<<<5120, 256>>>(conv_w);

    dim3 cg(LL / 256, 4, BB);
    k_conv_mma<<<cg, 256, SMEM_TOTAL>>>(x, conv_b, score_w);

    k_sreduce<<<(BB * LL) / 256, 256>>>();
    k_att<<<dim3(LL / 256, BB), 256>>>();
    k_combine<<<dim3(LOUT / 128, BB), 256>>>(out);
}

// round 6
// speedup vs baseline: 4.2500x; 1.9593x over previous
#include <cuda_runtime.h>
#include <cuda_fp16.h>
#include <cstdint>

// ---------------- problem constants ----------------
#define BB   8
#define EE   512
#define LL   8192
#define KS   5
#define LC   (LL - KS + 1)   // 8188
#define NB2  4094
#define NB3  2730
#define LOUT 4096

// ---------------- scratch ----------------
// prepped weights: [etile(4)*chunk(32)][tap(5)] 4KB swizzled fp16 images
__device__ __align__(16) char g_W2[4 * 32 * 5 * 4096];
__device__ float g_y[(size_t)BB * EE * LL];
__device__ float g_spart[4 * BB * LL];
__device__ float g_s[BB * LL];
__device__ float g_att[BB * LL * 3];

// ---------------- helpers ----------------
__device__ __forceinline__ uint32_t smem_to_u32(const void* p) {
    uint32_t a;
    asm("{ .reg .u64 t; cvta.to.shared.u64 t, %1; cvt.u32.u64 %0, t; }" : "=r"(a) : "l"(p));
    return a;
}
__device__ __forceinline__ void cp16(uint32_t s, const void* g) {
    asm volatile("cp.async.cg.shared.global [%0], [%1], 16;" :: "r"(s), "l"(g));
}
#define CP_COMMIT() asm volatile("cp.async.commit_group;")
#define CP_WAIT0()  asm volatile("cp.async.wait_group 0;" ::: "memory")

__device__ __forceinline__ void ldsm4(uint32_t* r, uint32_t addr) {
    asm volatile("ldmatrix.sync.aligned.m8n8.x4.shared.b16 {%0,%1,%2,%3}, [%4];"
        : "=r"(r[0]), "=r"(r[1]), "=r"(r[2]), "=r"(r[3]) : "r"(addr));
}
__device__ __forceinline__ void ldsm4t(uint32_t* r, uint32_t addr) {
    asm volatile("ldmatrix.sync.aligned.m8n8.x4.trans.shared.b16 {%0,%1,%2,%3}, [%4];"
        : "=r"(r[0]), "=r"(r[1]), "=r"(r[2]), "=r"(r[3]) : "r"(addr));
}
__device__ __forceinline__ void mma_fp16(float* d, const uint32_t* a, uint32_t b0, uint32_t b1) {
    asm volatile("mma.sync.aligned.m16n8k16.row.col.f32.f16.f16.f32 "
        "{%0,%1,%2,%3}, {%4,%5,%6,%7}, {%8,%9}, {%0,%1,%2,%3};"
        : "+f"(d[0]), "+f"(d[1]), "+f"(d[2]), "+f"(d[3])
        : "r"(a[0]), "r"(a[1]), "r"(a[2]), "r"(a[3]), "r"(b0), "r"(b1));
}

// ---------------- SMEM layout ----------------
#define WBUF_SZ 20480                 // 5 images x 4KB per chunk
#define XBUF0   (2 * WBUF_SZ)         // 40960
#define XIMG    12672                 // 264 rows x 48B (16 fp16 + 16B pad)
#define XBUF(buf) (XBUF0 + (buf) * XIMG)
#define SW_OFF  67584                 // beyond Ds staging (128*132*4 = 67584)
#define SMEM_TOTAL (SW_OFF + 512)     // 68096

// ---------------- kernel: prep W -> swizzled fp16 images ----------------
// image layout: byte = c*256 + ((e>>3)^(c&7))*16 + (e&7)*2  (c:0..15, e:0..127)
__global__ void k_prepW(const float* __restrict__ W) {
    int o = blockIdx.x * 256 + threadIdx.x;   // 4*32*5*16*128 = 1310720
    int e = o & 127;
    int c = (o >> 7) & 15;
    int rest = o >> 11;
    int tap = rest % 5;
    int ec = rest / 5;                        // etile*32 + chunk
    int e_g = (ec >> 5) * 128 + e;
    int c_g = (ec & 31) * 16 + c;
    float w = W[((size_t)e_g * EE + c_g) * KS + tap];
    size_t base = ((size_t)ec * 5 + tap) * 4096;
    uint32_t off = c * 256 + (((e >> 3) ^ (c & 7)) << 4) + (e & 7) * 2;
    *(__half*)(g_W2 + base + off) = __float2half(w);
}

// ---------------- X tile load / convert helpers (264 rows) ----------------
__device__ __forceinline__ void load_x_regs(const float* __restrict__ xb, int s, int t0,
                                            int wid, int lane, float* v0, float* v1) {
    const float* xr0 = xb + (size_t)(s * 16 + wid * 2) * LL;
    const float* xr1 = xr0 + LL;
    #pragma unroll
    for (int it = 0; it < 9; it++) {
        int t = lane + it * 32;
        bool act = (it < 8) || (lane < 8);
        int tg = t0 + t;
        bool inb = act && (tg < LL);
        v0[it] = inb ? __ldg(xr0 + tg) : 0.f;
        v1[it] = inb ? __ldg(xr1 + tg) : 0.f;
    }
}
__device__ __forceinline__ void store_x_smem(char* smem, uint32_t xoff,
                                             int wid, int lane,
                                             const float* v0, const float* v1) {
    #pragma unroll
    for (int it = 0; it < 9; it++) {
        if (it == 8 && lane >= 8) break;
        int t = lane + it * 32;
        __half ha = __float2half(v0[it]);
        __half hb = __float2half(v1[it]);
        uint32_t hp = (uint32_t)__half_as_ushort(ha) |
                      ((uint32_t)__half_as_ushort(hb) << 16);
        uint32_t byteoff = (uint32_t)t * 48 + (uint32_t)wid * 4;
        *(uint32_t*)(smem + xoff + byteoff) = hp;
    }
}

// ---------------- kernel: conv via fp16 mma.sync, CTA 256t x 128e, warp 64x64 ----------------
__global__ void __launch_bounds__(256, 1)
k_conv_mma(const float* __restrict__ x, const float* __restrict__ bias,
           const float* __restrict__ score_w) {
    extern __shared__ __align__(128) char smem[];
    const uint32_t sb = smem_to_u32(smem);
    const int tid = threadIdx.x, wid = tid >> 5, lane = tid & 31;
    const int b = blockIdx.z;
    const int etile = blockIdx.y;
    const int e0g = etile * 128;
    const int t0 = blockIdx.x * 256;
    const int wt = wid >> 1;         // 0..3 : 64-t slice
    const int we = wid & 1;          // 0..1 : 64-e slice

    if (tid < 128) ((float*)(smem + SW_OFF))[tid] = score_w[e0g + tid];

    const float* xb = x + (size_t)b * EE * LL;
    const char* wsrc_base = g_W2 + (size_t)etile * 32 * 5 * 4096;

    // ldmatrix address components
    const int g = lane >> 3, i8 = lane & 7;
    const int a_row0 = wt * 64 + (g & 1) * 8 + i8;       // + mf*16 + tap
    const uint32_t a_col = (uint32_t)(g >> 1) * 16;
    const int b_c = (g & 1) * 8 + i8;
    const int b_e0 = we * 64 + (g >> 1) * 8;
    uint32_t boff[4];
    #pragma unroll
    for (int eb = 0; eb < 4; eb++) {
        int be = b_e0 + eb * 16;
        boff[eb] = (uint32_t)b_c * 256 + ((((be) >> 3) ^ (b_c & 7)) << 4);
    }

    float acc[128];
    #pragma unroll
    for (int k = 0; k < 128; k++) acc[k] = 0.f;

    // ---- prologue: chunk 0 ----
    {
        #pragma unroll
        for (int k = 0; k < 5; k++)
            cp16(sb + (uint32_t)(tid + k * 256) * 16, wsrc_base + (size_t)(tid + k * 256) * 16);
        CP_COMMIT();
        float v0[9], v1[9];
        load_x_regs(xb, 0, t0, wid, lane, v0, v1);
        store_x_smem(smem, XBUF(0), wid, lane, v0, v1);
        CP_WAIT0();
    }
    __syncthreads();

    for (int s = 0; s < 32; s++) {
        const int buf = s & 1;
        float v0[9], v1[9];
        if (s < 31) {
            const char* wsrc = wsrc_base + (size_t)(s + 1) * 5 * 4096;
            uint32_t wdst = sb + (uint32_t)(buf ^ 1) * WBUF_SZ;
            #pragma unroll
            for (int k = 0; k < 5; k++)
                cp16(wdst + (uint32_t)(tid + k * 256) * 16, wsrc + (size_t)(tid + k * 256) * 16);
            CP_COMMIT();
            load_x_regs(xb, s + 1, t0, wid, lane, v0, v1);
        }

        // ---- compute chunk s ----
        const uint32_t xh = sb + XBUF(buf);
        const uint32_t wb = sb + (uint32_t)buf * WBUF_SZ;
        #pragma unroll
        for (int tap = 0; tap < 5; tap++) {
            uint32_t ah[4][4];
            #pragma unroll
            for (int mf = 0; mf < 4; mf++) {
                const uint32_t ar = (uint32_t)(a_row0 + mf * 16 + tap) * 48 + a_col;
                ldsm4(ah[mf], xh + ar);
            }
            const uint32_t wh = wb + (uint32_t)tap * 4096;
            #pragma unroll
            for (int eb = 0; eb < 4; eb++) {
                uint32_t bh[4];
                ldsm4t(bh, wh + boff[eb]);
                #pragma unroll
                for (int mf = 0; mf < 4; mf++) {
                    #pragma unroll
                    for (int sub = 0; sub < 2; sub++) {
                        float* D = acc + (mf * 8 + eb * 2 + sub) * 4;
                        mma_fp16(D, ah[mf], bh[sub * 2], bh[sub * 2 + 1]);
                    }
                }
            }
        }

        if (s < 31) {
            store_x_smem(smem, XBUF(buf ^ 1), wid, lane, v0, v1);
            CP_WAIT0();
        }
        __syncthreads();
    }

    // ---- epilogue: two t-halves of 128, staged in Ds[128e][132t] ----
    float* Ds = (float*)smem;
    const float* swp = (const float*)(smem + SW_OFF);
    const int tq = lane >> 2, eq = (lane & 3) << 1;
    float* sp = g_spart + (size_t)etile * (BB * LL) + (size_t)b * LL + t0;

    #pragma unroll
    for (int p = 0; p < 2; p++) {
        __syncthreads();
        if ((wt >> 1) == p) {
            const int wrow = wt & 1;
            #pragma unroll
            for (int nf = 0; nf < 8; nf++) {
                const int el = we * 64 + nf * 8 + eq;
                const float b0 = __ldg(bias + e0g + el);
                const float b1 = __ldg(bias + e0g + el + 1);
                #pragma unroll
                for (int mf = 0; mf < 4; mf++) {
                    const int tl = wrow * 64 + mf * 16 + tq;
                    const int tg = t0 + p * 128 + tl;
                    const bool ok0 = tg < LC;
                    const bool ok1 = (tg + 8) < LC;
                    const float* A = acc + (mf * 8 + nf) * 4;
                    Ds[(size_t)el * 132 + tl]           = ok0 ? A[0] + b0 : 0.f;
                    Ds[(size_t)(el + 1) * 132 + tl]     = ok0 ? A[1] + b1 : 0.f;
                    Ds[(size_t)el * 132 + tl + 8]       = ok1 ? A[2] + b0 : 0.f;
                    Ds[(size_t)(el + 1) * 132 + tl + 8] = ok1 ? A[3] + b1 : 0.f;
                }
            }
        }
        __syncthreads();

        // y store (coalesced)
        float* yb = g_y + ((size_t)b * EE + e0g) * LL + t0 + p * 128;
        #pragma unroll
        for (int rr = 0; rr < 16; rr++) {
            int e = wid * 16 + rr;
            #pragma unroll
            for (int tb = 0; tb < 4; tb++)
                yb[(size_t)e * LL + tb * 32 + lane] = Ds[(size_t)e * 132 + tb * 32 + lane];
        }
        // fused score partials
        {
            int tl = tid >> 3, er = tid & 7;
            #pragma unroll
            for (int tb = 0; tb < 4; tb++) {
                float a = 0.f;
                #pragma unroll 4
                for (int k = 0; k < 16; k++) {
                    int e = er * 16 + k;
                    a += Ds[(size_t)e * 132 + tb * 32 + tl] * swp[e];
                }
                a += __shfl_xor_sync(0xffffffff, a, 1);
                a += __shfl_xor_sync(0xffffffff, a, 2);
                a += __shfl_xor_sync(0xffffffff, a, 4);
                if (er == 0) sp[p * 128 + tb * 32 + tl] = a;
            }
        }
    }
}

// ---------------- kernel: deterministic 4-way score reduce ----------------
__global__ void k_sreduce() {
    int i = blockIdx.x * 256 + threadIdx.x;
    g_s[i] = (g_spart[i] + g_spart[BB * LL + i]) +
             (g_spart[2 * BB * LL + i] + g_spart[3 * BB * LL + i]);
}

// ---------------- kernel: softmax over 3 widths ----------------
__global__ void k_att() {
    int b = blockIdx.y;
    int t = blockIdx.x * 256 + threadIdx.x;
    const float* s = g_s + b * LL;
    float sc1 = (t < LC) ? s[t] : 0.f;
    int n2 = t >> 1;
    float sc2 = (n2 < NB2) ? 0.5f * (s[2 * n2] + s[2 * n2 + 1]) : 0.f;
    int n3 = t / 3;
    float sc3 = (n3 < NB3) ? (s[3 * n3] + s[3 * n3 + 1] + s[3 * n3 + 2]) * (1.f / 3.f) : 0.f;
    float m  = fmaxf(sc1, fmaxf(sc2, sc3));
    float e1 = expf(sc1 - m);
    float e2 = expf(sc2 - m);
    float e3 = expf(sc3 - m);
    float inv = 1.f / (e1 + e2 + e3);
    float* ap = g_att + ((size_t)b * LL + t) * 3;
    ap[0] = e1 * inv;
    ap[1] = e2 * inv;
    ap[2] = e3 * inv;
}

// ---------------- kernel: blend widths + downsample (att cached in smem) ----------------
__global__ void k_combine(float* __restrict__ out) {
    // grid: (LOUT/128, BB), block 256
    __shared__ float satt[768];
    const int tid = threadIdx.x;
    const int b = blockIdx.y;
    const int tdblk = blockIdx.x;
    const int tbase = tdblk * 256;
    const float* ag = g_att + ((size_t)b * LL + tbase) * 3;
    for (int i = tid; i < 768; i += 256) satt[i] = ag[i];
    __syncthreads();

    const int tdl = tid & 127;
    const int td = tdblk * 128 + tdl;
    const int baseg = td * 2;
    const int basel = tdl * 2;

    const float a0 = satt[basel * 3 + 0], a1 = satt[basel * 3 + 1], a2 = satt[basel * 3 + 2];
    const float a3 = satt[basel * 3 + 3], a4 = satt[basel * 3 + 4], a5 = satt[basel * 3 + 5];

    const int r = baseg % 3;
    const bool ok3_0 = (baseg / 3) < NB3;
    const bool ok3_1 = ((baseg + 1) / 3) < NB3;
    const bool ok2 = td < NB2;

    for (int e = (tid >> 7); e < EE; e += 2) {
        const float* yrow = g_y + ((size_t)b * EE + e) * LL;
        float w[6];
        #pragma unroll
        for (int d = 0; d < 6; d++) {
            int idx = baseg + d - 2;
            w[d] = (idx >= 0 && idx < LL) ? yrow[idx] : 0.f;
        }
        float v1_0 = w[2];
        float v1_1 = w[3];
        float v2   = ok2 ? 0.5f * (w[2] + w[3]) : 0.f;

        float p0 = w[0] + w[1] + w[2];
        float p1 = w[1] + w[2] + w[3];
        float p2 = w[2] + w[3] + w[4];
        float p3 = w[3] + w[4] + w[5];
        float s0 = (r == 0) ? p2 : ((r == 1) ? p1 : p0);
        float s1 = (r == 0) ? p2 : ((r == 1) ? p1 : p3);
        float v3_0 = ok3_0 ? s0 * (1.f / 3.f) : 0.f;
        float v3_1 = ok3_1 ? s1 * (1.f / 3.f) : 0.f;

        out[((size_t)b * EE + e) * LOUT + td] =
            0.5f * (a0 * v1_0 + a1 * v2 + a2 * v3_0 +
                    a3 * v1_1 + a4 * v2 + a5 * v3_1);
    }
}

// ---------------- launcher ----------------
extern "C" void kernel_launch(void* const* d_in, const int* in_sizes, int n_in,
                              void* d_out, int out_size) {
    const float* x       = (const float*)d_in[0];
    const float* conv_w  = (const float*)d_in[1];
    const float* conv_b  = (const float*)d_in[2];
    const float* score_w = (const float*)d_in[3];
    float* out = (float*)d_out;

    cudaFuncSetAttribute(k_conv_mma, cudaFuncAttributeMaxDynamicSharedMemorySize, SMEM_TOTAL);

    k_prepW<<<5120, 256>>>(conv_w);

    dim3 cg(LL / 256, 4, BB);
    k_conv_mma<<<cg, 256, SMEM_TOTAL>>>(x, conv_b, score_w);

    k_sreduce<<<(BB * LL) / 256, 256>>>();
    k_att<<<dim3(LL / 256, BB), 256>>>();
    k_combine<<<dim3(LOUT / 128, BB), 256>>>(out);
}